// round 2
// baseline (speedup 1.0000x reference)
#include <cuda_runtime.h>
#include <math_constants.h>
#include <cstdint>
#include <cstddef>

// Problem constants
#define BB 2
#define TT 2048
#define HH 1024
#define VV 50257
#define MTOT (BB*TT)        // 4096

// GEMM tiling
#define BM 128
#define BN 128
#define BK 16
#define SAS (BK+4)          // 20-float smem row stride -> conflict-free frag loads
#define NTHREADS 256

__device__ float g_nll[BB*(TT-1)];   // per-row NLL scratch (4094 entries)

__device__ __forceinline__ unsigned cvt_tf32(float x) {
    unsigned u;
    asm("cvt.rna.tf32.f32 %0, %1;" : "=r"(u) : "f"(x));
    return u;
}

__device__ __forceinline__ void mma_tf32(float* c,
    unsigned a0, unsigned a1, unsigned a2, unsigned a3,
    unsigned b0, unsigned b1)
{
    asm volatile("mma.sync.aligned.m16n8k8.row.col.f32.tf32.tf32.f32 "
        "{%0,%1,%2,%3}, {%4,%5,%6,%7}, {%8,%9}, {%0,%1,%2,%3};"
        : "+f"(c[0]), "+f"(c[1]), "+f"(c[2]), "+f"(c[3])
        : "r"(a0), "r"(a1), "r"(a2), "r"(a3), "r"(b0), "r"(b1));
}

__device__ __forceinline__ void cp16(float* dst, const float* src, int szbytes) {
    unsigned s = (unsigned)__cvta_generic_to_shared(dst);
    asm volatile("cp.async.cg.shared.global [%0], [%1], 16, %2;"
                 :: "r"(s), "l"(src), "r"(szbytes));
}

// C[m, n] = sum_k A[m, k] * W[n, k]
// A: [4096, 1024] row-major, W: [50257, 1024] row-major, C: [4096, 50257]
__global__ void __launch_bounds__(NTHREADS)
gemm_tf32_kernel(const float* __restrict__ A, const float* __restrict__ W,
                 float* __restrict__ C)
{
    __shared__ float sA[2][BM][SAS];
    __shared__ float sB[2][BN][SAS];

    const int bm = blockIdx.x;     // M tile (x = fast dim -> A tiles stay L2-hot)
    const int bn = blockIdx.y;     // N tile
    const int tid = threadIdx.x;
    const int lane = tid & 31;
    const int warp = tid >> 5;
    const int warpM = warp >> 2;   // 0..1 -> 64 rows
    const int warpN = warp & 3;    // 0..3 -> 32 cols
    const int grp = lane >> 2;     // 0..7
    const int tg  = lane & 3;      // 0..3

    const int rowA0 = bm * BM;
    const int rowB0 = bn * BN;

    float acc[4][4][4];
    #pragma unroll
    for (int i = 0; i < 4; i++)
        #pragma unroll
        for (int j = 0; j < 4; j++)
            #pragma unroll
            for (int k = 0; k < 4; k++) acc[i][j][k] = 0.f;

    // Stage loader: 128 rows x 16 floats per tile = 512 16B-chunks; 2/thread/tile.
    auto load_stage = [&](int stage, int kt) {
        const int k0 = kt * BK;
        #pragma unroll
        for (int i = 0; i < 2; i++) {
            int id = tid + i * NTHREADS;
            int r = id >> 2;
            int cc = (id & 3) * 4;
            cp16(&sA[stage][r][cc], A + (size_t)(rowA0 + r) * HH + k0 + cc, 16);
        }
        #pragma unroll
        for (int i = 0; i < 2; i++) {
            int id = tid + i * NTHREADS;
            int r = id >> 2;
            int cc = (id & 3) * 4;
            int n = rowB0 + r;
            bool ok = (n < VV);
            const float* src = W + (size_t)(ok ? n : 0) * HH + k0 + cc;
            cp16(&sB[stage][r][cc], src, ok ? 16 : 0);   // zero-fill OOB rows
        }
        asm volatile("cp.async.commit_group;");
    };

    load_stage(0, 0);

    const int NK = HH / BK;   // 64
    for (int kt = 0; kt < NK; kt++) {
        const int cur = kt & 1;
        if (kt + 1 < NK) {
            load_stage(cur ^ 1, kt + 1);
            asm volatile("cp.async.wait_group 1;");
        } else {
            asm volatile("cp.async.wait_group 0;");
        }
        __syncthreads();

        #pragma unroll
        for (int ks = 0; ks < 2; ks++) {
            const int kb = ks * 8;
            unsigned af[4][4], bf[4][2];
            #pragma unroll
            for (int mt = 0; mt < 4; mt++) {
                int r = warpM * 64 + mt * 16 + grp;
                af[mt][0] = cvt_tf32(sA[cur][r    ][kb + tg    ]);
                af[mt][1] = cvt_tf32(sA[cur][r + 8][kb + tg    ]);
                af[mt][2] = cvt_tf32(sA[cur][r    ][kb + tg + 4]);
                af[mt][3] = cvt_tf32(sA[cur][r + 8][kb + tg + 4]);
            }
            #pragma unroll
            for (int nt = 0; nt < 4; nt++) {
                int c = warpN * 32 + nt * 8 + grp;
                bf[nt][0] = cvt_tf32(sB[cur][c][kb + tg    ]);
                bf[nt][1] = cvt_tf32(sB[cur][c][kb + tg + 4]);
            }
            #pragma unroll
            for (int mt = 0; mt < 4; mt++)
                #pragma unroll
                for (int nt = 0; nt < 4; nt++)
                    mma_tf32(acc[mt][nt],
                             af[mt][0], af[mt][1], af[mt][2], af[mt][3],
                             bf[nt][0], bf[nt][1]);
        }
        __syncthreads();
    }

    // Epilogue (scalar stores; row stride VV is odd so no 8B-aligned vector stores)
    #pragma unroll
    for (int mt = 0; mt < 4; mt++) {
        const int r0 = rowA0 + warpM * 64 + mt * 16 + grp;
        #pragma unroll
        for (int nt = 0; nt < 4; nt++) {
            const int c0 = rowB0 + warpN * 32 + nt * 8 + tg * 2;
            if (c0 < VV) {
                size_t base  = (size_t)r0 * VV + c0;
                size_t base2 = base + (size_t)8 * VV;
                C[base]  = acc[mt][nt][0];
                C[base2] = acc[mt][nt][2];
                if (c0 + 1 < VV) {
                    C[base + 1]  = acc[mt][nt][1];
                    C[base2 + 1] = acc[mt][nt][3];
                }
            }
        }
    }
}

// One block per shifted row: online logsumexp over V, nll = lse - logit[label].
// NOTE: labels are int32 (JAX silently downcasts int64 without x64 enabled).
__global__ void __launch_bounds__(256)
loss_rows_kernel(const float* __restrict__ logits, const int* __restrict__ labels)
{
    const int r = blockIdx.x;               // 0..4093
    const int b = r / (TT - 1);
    const int t = r - b * (TT - 1);
    const float* row = logits + (size_t)(b * TT + t) * VV;

    float m = -CUDART_INF_F, s = 0.f;
    for (int i = threadIdx.x; i < VV; i += 256) {
        float x = row[i];
        if (x > m) { s = s * __expf(m - x) + 1.f; m = x; }
        else       { s += __expf(x - m); }
    }
    // warp-level (m, s) combine
    #pragma unroll
    for (int o = 16; o; o >>= 1) {
        float mo = __shfl_down_sync(0xffffffffu, m, o);
        float so = __shfl_down_sync(0xffffffffu, s, o);
        float M = fmaxf(m, mo);
        s = s * __expf(m - M) + so * __expf(mo - M);
        m = M;
    }
    __shared__ float sm_[8], ss_[8];
    const int lane = threadIdx.x & 31, w = threadIdx.x >> 5;
    if (lane == 0) { sm_[w] = m; ss_[w] = s; }
    __syncthreads();
    if (w == 0) {
        m = (lane < 8) ? sm_[lane] : -CUDART_INF_F;
        s = (lane < 8) ? ss_[lane] : 0.f;
        #pragma unroll
        for (int o = 4; o; o >>= 1) {
            float mo = __shfl_down_sync(0xffffffffu, m, o);
            float so = __shfl_down_sync(0xffffffffu, s, o);
            float M = fmaxf(m, mo);
            s = s * __expf(m - M) + so * __expf(mo - M);
            m = M;
        }
        if (lane == 0) {
            int lbl = labels[b * TT + t + 1];
            if (lbl < 0) lbl = 0;
            if (lbl >= VV) lbl = VV - 1;
            float lse = m + __logf(s);
            g_nll[r] = lse - row[lbl];
        }
    }
}

// Deterministic mean of the 4094 per-row NLLs -> out_loss.
__global__ void __launch_bounds__(256)
loss_reduce_kernel(float* __restrict__ out_loss)
{
    __shared__ float sh[256];
    float v = 0.f;
    for (int i = threadIdx.x; i < BB * (TT - 1); i += 256) v += g_nll[i];
    sh[threadIdx.x] = v;
    __syncthreads();
    for (int st = 128; st; st >>= 1) {
        if (threadIdx.x < st) sh[threadIdx.x] += sh[threadIdx.x + st];
        __syncthreads();
    }
    if (threadIdx.x == 0) *out_loss = sh[0] / (float)(BB * (TT - 1));
}

extern "C" void kernel_launch(void* const* d_in, const int* in_sizes, int n_in,
                              void* d_out, int out_size)
{
    // Resolve inputs by element count (robust to metadata ordering):
    //   hidden_states: 2*2048*1024 = 4194304 fp32
    //   weight:        50257*1024  = 51463168 fp32
    //   labels:        2*2048      = 4096 int32
    const float* hidden = nullptr;
    const float* weight = nullptr;
    const int*   labels = nullptr;
    for (int i = 0; i < n_in; i++) {
        if      (in_sizes[i] == MTOT * HH)      hidden = (const float*)d_in[i];
        else if (in_sizes[i] == VV * HH)        weight = (const float*)d_in[i];
        else if (in_sizes[i] == BB * TT)        labels = (const int*)d_in[i];
    }
    float* out = (float*)d_out;   // [B*T*V] logits, then scalar loss at the end

    dim3 grid(MTOT / BM, (VV + BN - 1) / BN);            // (32, 393), x = M fast
    gemm_tf32_kernel<<<grid, NTHREADS>>>(hidden, weight, out);
    loss_rows_kernel<<<BB * (TT - 1), 256>>>(out, labels);
    loss_reduce_kernel<<<1, 256>>>(out + (size_t)out_size - 1);
}

// round 6
// speedup vs baseline: 1.3419x; 1.3419x over previous
#include <cuda_runtime.h>
#include <math_constants.h>
#include <cstdint>
#include <cstddef>

// ---------------- Problem constants ----------------
#define BB 2
#define TT 2048
#define HH 1024
#define VV 50257
#define MTOT (BB*TT)          // 4096
#define NT 393                // ceil(50257/128) N tiles

// ---------------- GEMM tiling ----------------
#define TM 128
#define TN 128
#define TK 16                 // K per stage
#define NST 4                 // pipeline stages
#define NK (HH/TK)            // 64 K iterations
#define NTHREADS 256

#define A_ST 8192             // TM*TK*4 bytes per A stage
#define B_ST 8192             // TN*TK*4 bytes per B stage
#define ST   (A_ST+B_ST)      // 16384
#define SMEM_TOTAL (NST*ST)   // 65536 (dynamic)

// ---------------- device scratch ----------------
// A_packed: [mtile 0..31][kt 0..63] tiles of 8KB, fragment order:
//   unit16B v = block(0..7)*64 + slab(0..1)*32 + lane(0..31)
//   regs = A[r0][c0], A[r0+8][c0], A[r0][c0+4], A[r0+8][c0+4]
//   r0 = mtile*128+block*16+(lane>>2), c0 = kt*16+slab*8+(lane&3)
__device__ float A_packed[MTOT*HH];                    // 16 MB
// W_packed: [ntile 0..392][kt 0..63] tiles of 8KB:
//   unit16B v = cb(0..15)*32 + lane
//   regs = W[n][c], W[n][c+4], W[n][c+8], W[n][c+12]
//   n = ntile*128+cb*8+(lane>>2), c = kt*16+(lane&3)
__device__ float W_packed[(size_t)NT*64*2048];         // ~206 MB
__device__ float g_nll[BB*(TT-1)];

// ---------------- helpers ----------------
__device__ __forceinline__ unsigned cvt_tf32(float x) {
    unsigned u; asm("cvt.rna.tf32.f32 %0, %1;" : "=r"(u) : "f"(x)); return u;
}
__device__ __forceinline__ void mma_tf32(float* c,
    unsigned a0, unsigned a1, unsigned a2, unsigned a3,
    unsigned b0, unsigned b1)
{
    asm volatile("mma.sync.aligned.m16n8k8.row.col.f32.tf32.tf32.f32 "
        "{%0,%1,%2,%3}, {%4,%5,%6,%7}, {%8,%9}, {%0,%1,%2,%3};"
        : "+f"(c[0]), "+f"(c[1]), "+f"(c[2]), "+f"(c[3])
        : "r"(a0), "r"(a1), "r"(a2), "r"(a3), "r"(b0), "r"(b1));
}
__device__ __forceinline__ void cp16(void* dst, const void* src) {
    unsigned s = (unsigned)__cvta_generic_to_shared(dst);
    asm volatile("cp.async.cg.shared.global [%0], [%1], 16;" :: "r"(s), "l"(src));
}

// ---------------- pack kernels ----------------
__global__ void __launch_bounds__(256)
pack_A_kernel(const float* __restrict__ src)
{
    int idx  = blockIdx.x * 256 + threadIdx.x;     // 16B unit id, 1M total
    int tile = idx >> 9;                            // 512 units per tile
    int v    = idx & 511;
    int mtile = tile >> 6, kt = tile & 63;
    int block = v >> 6, rem = v & 63;
    int slab  = rem >> 5, lane = rem & 31;
    int grp = lane >> 2, tg = lane & 3;
    int r0 = mtile * 128 + block * 16 + grp;
    int c0 = kt * 16 + slab * 8 + tg;
    const float* p = src + (size_t)r0 * HH + c0;
    float4 o;
    o.x = __uint_as_float(cvt_tf32(p[0]));
    o.y = __uint_as_float(cvt_tf32(p[8 * HH]));
    o.z = __uint_as_float(cvt_tf32(p[4]));
    o.w = __uint_as_float(cvt_tf32(p[8 * HH + 4]));
    ((float4*)A_packed)[idx] = o;
}

__global__ void __launch_bounds__(256)
pack_W_kernel(const float* __restrict__ src)
{
    int idx  = blockIdx.x * 256 + threadIdx.x;     // 16B unit id, NT*64*512 total
    int tile = idx >> 9;
    int v    = idx & 511;
    int ntile = tile >> 6, kt = tile & 63;
    int cb = v >> 5, lane = v & 31;
    int grp = lane >> 2, tg = lane & 3;
    int n = ntile * 128 + cb * 8 + grp;
    int c = kt * 16 + tg;
    float4 o = make_float4(0.f, 0.f, 0.f, 0.f);
    if (n < VV) {
        const float* p = src + (size_t)n * HH + c;
        o.x = __uint_as_float(cvt_tf32(p[0]));
        o.y = __uint_as_float(cvt_tf32(p[4]));
        o.z = __uint_as_float(cvt_tf32(p[8]));
        o.w = __uint_as_float(cvt_tf32(p[12]));
    }
    ((float4*)W_packed)[idx] = o;
}

// ---------------- GEMM: C[4096,50257] = A @ W^T ----------------
__global__ void __launch_bounds__(NTHREADS, 2)
gemm_tf32_kernel(float* __restrict__ C)
{
    extern __shared__ char smem[];

    const int bm = blockIdx.x;     // M tile (fast dim -> A stays L2 hot)
    const int bn = blockIdx.y;     // N tile
    const int tid = threadIdx.x;
    const int lane = tid & 31;
    const int warp = tid >> 5;
    const int warpM = warp >> 2;   // 0..1
    const int warpN = warp & 3;    // 0..3

    const char* Abase = (const char*)A_packed + (size_t)bm * 64 * A_ST;
    const char* Bbase = (const char*)W_packed + (size_t)bn * 64 * B_ST;

    float acc[4][4][4];
    #pragma unroll
    for (int i = 0; i < 4; i++)
        #pragma unroll
        for (int j = 0; j < 4; j++)
            #pragma unroll
            for (int k = 0; k < 4; k++) acc[i][j][k] = 0.f;

    // Stage loader: 1024 x 16B chunks (A first 512, B next 512), 4 per thread.
    auto load_stage = [&](int kt) {
        char* stg = smem + (kt & (NST - 1)) * ST;
        const char* asrc = Abase + (size_t)kt * A_ST;
        const char* bsrc = Bbase + (size_t)kt * B_ST;
        #pragma unroll
        for (int i = 0; i < 2; i++) {
            int j = tid + i * NTHREADS;            // 0..511 -> A
            cp16(stg + j * 16, asrc + j * 16);
        }
        #pragma unroll
        for (int i = 0; i < 2; i++) {
            int j = tid + i * NTHREADS;            // 0..511 -> B
            cp16(stg + A_ST + j * 16, bsrc + j * 16);
        }
        asm volatile("cp.async.commit_group;");
    };

    load_stage(0); load_stage(1); load_stage(2);

    for (int kt = 0; kt < NK; kt++) {
        if (kt + 3 < NK) {
            load_stage(kt + 3);
            asm volatile("cp.async.wait_group 3;");
        } else {
            asm volatile("cp.async.wait_group 0;");
        }
        __syncthreads();   // stage kt visible to all warps

        const char* stg = smem + (kt & (NST - 1)) * ST;
        const char* sA = stg + (size_t)(warpM * 4) * 1024 + lane * 16;
        const char* sB = stg + A_ST + (size_t)(warpN * 4) * 512 + lane * 16;

        // B fragments: 16B per (nt) covers both K=8 slabs
        uint4 bf[4];
        #pragma unroll
        for (int nt = 0; nt < 4; nt++)
            bf[nt] = *(const uint4*)(sB + nt * 512);

        #pragma unroll
        for (int slab = 0; slab < 2; slab++) {
            uint4 af[4];
            #pragma unroll
            for (int mt = 0; mt < 4; mt++)
                af[mt] = *(const uint4*)(sA + mt * 1024 + slab * 512);
            #pragma unroll
            for (int mt = 0; mt < 4; mt++)
                #pragma unroll
                for (int nt = 0; nt < 4; nt++) {
                    unsigned b0 = slab ? bf[nt].z : bf[nt].x;
                    unsigned b1 = slab ? bf[nt].w : bf[nt].y;
                    mma_tf32(acc[mt][nt], af[mt].x, af[mt].y, af[mt].z, af[mt].w, b0, b1);
                }
        }
        __syncthreads();   // all warps done with stage kt before it is overwritten
    }

    // Epilogue
    const int grp = lane >> 2, tg = lane & 3;
    #pragma unroll
    for (int mt = 0; mt < 4; mt++) {
        const int r0 = bm * TM + warpM * 64 + mt * 16 + grp;
        #pragma unroll
        for (int nt = 0; nt < 4; nt++) {
            const int c0 = bn * TN + warpN * 32 + nt * 8 + tg * 2;
            if (c0 < VV) {
                size_t base  = (size_t)r0 * VV + c0;
                size_t base2 = base + (size_t)8 * VV;
                C[base]  = acc[mt][nt][0];
                C[base2] = acc[mt][nt][2];
                if (c0 + 1 < VV) {
                    C[base + 1]  = acc[mt][nt][1];
                    C[base2 + 1] = acc[mt][nt][3];
                }
            }
        }
    }
}

// ---------------- loss ----------------
__global__ void __launch_bounds__(256)
loss_rows_kernel(const float* __restrict__ logits, const int* __restrict__ labels)
{
    const int r = blockIdx.x;               // 0..4093
    const int b = r / (TT - 1);
    const int t = r - b * (TT - 1);
    const float* row = logits + (size_t)(b * TT + t) * VV;

    float m = -CUDART_INF_F, s = 0.f;
    for (int i = threadIdx.x; i < VV; i += 256) {
        float x = row[i];
        if (x > m) { s = s * __expf(m - x) + 1.f; m = x; }
        else       { s += __expf(x - m); }
    }
    #pragma unroll
    for (int o = 16; o; o >>= 1) {
        float mo = __shfl_down_sync(0xffffffffu, m, o);
        float so = __shfl_down_sync(0xffffffffu, s, o);
        float M = fmaxf(m, mo);
        s = s * __expf(m - M) + so * __expf(mo - M);
        m = M;
    }
    __shared__ float sm_[8], ss_[8];
    const int lane = threadIdx.x & 31, w = threadIdx.x >> 5;
    if (lane == 0) { sm_[w] = m; ss_[w] = s; }
    __syncthreads();
    if (w == 0) {
        m = (lane < 8) ? sm_[lane] : -CUDART_INF_F;
        s = (lane < 8) ? ss_[lane] : 0.f;
        #pragma unroll
        for (int o = 4; o; o >>= 1) {
            float mo = __shfl_down_sync(0xffffffffu, m, o);
            float so = __shfl_down_sync(0xffffffffu, s, o);
            float M = fmaxf(m, mo);
            s = s * __expf(m - M) + so * __expf(mo - M);
            m = M;
        }
        if (lane == 0) {
            int lbl = labels[b * TT + t + 1];
            if (lbl < 0) lbl = 0;
            if (lbl >= VV) lbl = VV - 1;
            g_nll[r] = m + __logf(s) - row[lbl];
        }
    }
}

__global__ void __launch_bounds__(256)
loss_reduce_kernel(float* __restrict__ out_loss)
{
    __shared__ float sh[256];
    float v = 0.f;
    for (int i = threadIdx.x; i < BB * (TT - 1); i += 256) v += g_nll[i];
    sh[threadIdx.x] = v;
    __syncthreads();
    for (int st = 128; st; st >>= 1) {
        if (threadIdx.x < st) sh[threadIdx.x] += sh[threadIdx.x + st];
        __syncthreads();
    }
    if (threadIdx.x == 0) *out_loss = sh[0] / (float)(BB * (TT - 1));
}

// ---------------- launch ----------------
extern "C" void kernel_launch(void* const* d_in, const int* in_sizes, int n_in,
                              void* d_out, int out_size)
{
    const float* hidden = nullptr;
    const float* weight = nullptr;
    const int*   labels = nullptr;
    for (int i = 0; i < n_in; i++) {
        if      (in_sizes[i] == MTOT * HH) hidden = (const float*)d_in[i];
        else if (in_sizes[i] == VV * HH)   weight = (const float*)d_in[i];
        else if (in_sizes[i] == BB * TT)   labels = (const int*)d_in[i];
    }
    float* out = (float*)d_out;

    cudaFuncSetAttribute(gemm_tf32_kernel,
                         cudaFuncAttributeMaxDynamicSharedMemorySize, SMEM_TOTAL);

    pack_A_kernel<<<(MTOT * HH / 4) / 256, 256>>>(hidden);
    pack_W_kernel<<<(NT * 64 * 512) / 256, 256>>>(weight);

    dim3 grid(MTOT / TM, NT);          // (32, 393)
    gemm_tf32_kernel<<<grid, NTHREADS, SMEM_TOTAL>>>(out);

    loss_rows_kernel<<<BB * (TT - 1), 256>>>(out, labels);
    loss_reduce_kernel<<<1, 256>>>(out + (size_t)out_size - 1);
}

// round 7
// speedup vs baseline: 1.4586x; 1.0869x over previous
#include <cuda_runtime.h>
#include <math_constants.h>
#include <cstdint>
#include <cstddef>

// ---------------- Problem constants ----------------
#define BB 2
#define TT 2048
#define HH 1024
#define VV 50257
#define MTOT (BB*TT)          // 4096
#define NT 393                // ceil(50257/128) N tiles

// ---------------- GEMM tiling ----------------
#define TM 128
#define TN 128
#define TK 16                 // K per stage
#define NST 4                 // pipeline stages
#define NK (HH/TK)            // 64 K iterations
#define NTHREADS 128          // 4 warps, each m64n64

#define A_ST 8192             // TM*TK*4 bytes per A stage
#define B_ST 8192             // TN*TK*4 bytes per B stage
#define ST   (A_ST+B_ST)      // 16384
#define SMEM_TOTAL (NST*ST)   // 65536 (dynamic)

// ---------------- device scratch ----------------
// A_packed: [mtile 0..31][kt 0..63] tiles of 8KB, fragment order:
//   unit16B v = block(0..7)*64 + slab(0..1)*32 + lane(0..31)
//   regs = A[r0][c0], A[r0+8][c0], A[r0][c0+4], A[r0+8][c0+4]
//   r0 = mtile*128+block*16+(lane>>2), c0 = kt*16+slab*8+(lane&3)
__device__ float A_packed[MTOT*HH];                    // 16 MB
// W_packed: [ntile 0..392][kt 0..63] tiles of 8KB:
//   unit16B v = cb(0..15)*32 + lane
//   regs = W[n][c], W[n][c+4], W[n][c+8], W[n][c+12]
//   n = ntile*128+cb*8+(lane>>2), c = kt*16+(lane&3)
__device__ float W_packed[(size_t)NT*64*2048];         // ~206 MB
__device__ float g_nll[BB*(TT-1)];
__device__ float part_m[(size_t)MTOT*NT];              // per-(row, ntile) lse partials
__device__ float part_s[(size_t)MTOT*NT];              // 2 x 6.4 MB

// ---------------- helpers ----------------
__device__ __forceinline__ unsigned cvt_tf32(float x) {
    unsigned u; asm("cvt.rna.tf32.f32 %0, %1;" : "=r"(u) : "f"(x)); return u;
}
__device__ __forceinline__ void mma_tf32(float* c,
    unsigned a0, unsigned a1, unsigned a2, unsigned a3,
    unsigned b0, unsigned b1)
{
    asm volatile("mma.sync.aligned.m16n8k8.row.col.f32.tf32.tf32.f32 "
        "{%0,%1,%2,%3}, {%4,%5,%6,%7}, {%8,%9}, {%0,%1,%2,%3};"
        : "+f"(c[0]), "+f"(c[1]), "+f"(c[2]), "+f"(c[3])
        : "r"(a0), "r"(a1), "r"(a2), "r"(a3), "r"(b0), "r"(b1));
}
__device__ __forceinline__ void cp16(void* dst, const void* src) {
    unsigned s = (unsigned)__cvta_generic_to_shared(dst);
    asm volatile("cp.async.cg.shared.global [%0], [%1], 16;" :: "r"(s), "l"(src));
}
// -inf-safe (m, s) logsumexp-state combine; fixed order -> deterministic
__device__ __forceinline__ void lse_comb(float& m, float& s, float mo, float so) {
    float M = fmaxf(m, mo);
    if (M == -CUDART_INF_F) { m = M; s = 0.f; return; }
    s = s * __expf(m - M) + so * __expf(mo - M);
    m = M;
}

// ---------------- pack kernels ----------------
__global__ void __launch_bounds__(256)
pack_A_kernel(const float* __restrict__ src)
{
    int idx  = blockIdx.x * 256 + threadIdx.x;     // 16B unit id
    int tile = idx >> 9;                            // 512 units per tile
    int v    = idx & 511;
    int mtile = tile >> 6, kt = tile & 63;
    int block = v >> 6, rem = v & 63;
    int slab  = rem >> 5, lane = rem & 31;
    int grp = lane >> 2, tg = lane & 3;
    int r0 = mtile * 128 + block * 16 + grp;
    int c0 = kt * 16 + slab * 8 + tg;
    const float* p = src + (size_t)r0 * HH + c0;
    float4 o;
    o.x = __uint_as_float(cvt_tf32(p[0]));
    o.y = __uint_as_float(cvt_tf32(p[8 * HH]));
    o.z = __uint_as_float(cvt_tf32(p[4]));
    o.w = __uint_as_float(cvt_tf32(p[8 * HH + 4]));
    ((float4*)A_packed)[idx] = o;
}

__global__ void __launch_bounds__(256)
pack_W_kernel(const float* __restrict__ src)
{
    int idx  = blockIdx.x * 256 + threadIdx.x;
    int tile = idx >> 9;
    int v    = idx & 511;
    int ntile = tile >> 6, kt = tile & 63;
    int cb = v >> 5, lane = v & 31;
    int grp = lane >> 2, tg = lane & 3;
    int n = ntile * 128 + cb * 8 + grp;
    int c = kt * 16 + tg;
    float4 o = make_float4(0.f, 0.f, 0.f, 0.f);
    if (n < VV) {
        const float* p = src + (size_t)n * HH + c;
        o.x = __uint_as_float(cvt_tf32(p[0]));
        o.y = __uint_as_float(cvt_tf32(p[4]));
        o.z = __uint_as_float(cvt_tf32(p[8]));
        o.w = __uint_as_float(cvt_tf32(p[12]));
    }
    ((float4*)W_packed)[idx] = o;
}

// ---------------- GEMM + fused lse partials ----------------
__global__ void __launch_bounds__(NTHREADS, 2)
gemm_tf32_kernel(float* __restrict__ C)
{
    extern __shared__ char smem[];
    __shared__ float sbm[2][128], sbs[2][128];   // [warpN][local row]

    const int bm = blockIdx.x;     // M tile (fast dim -> A stays L2 hot)
    const int bn = blockIdx.y;     // N tile
    const int tid = threadIdx.x;
    const int lane = tid & 31;
    const int warp = tid >> 5;
    const int warpM = warp >> 1;   // 0..1 -> 64 rows
    const int warpN = warp & 1;    // 0..1 -> 64 cols
    const int grp = lane >> 2, tg = lane & 3;

    const char* Abase = (const char*)A_packed + (size_t)bm * 64 * A_ST;
    const char* Bbase = (const char*)W_packed + (size_t)bn * 64 * B_ST;

    float acc[4][8][4];
    #pragma unroll
    for (int i = 0; i < 4; i++)
        #pragma unroll
        for (int j = 0; j < 8; j++)
            #pragma unroll
            for (int k = 0; k < 4; k++) acc[i][j][k] = 0.f;

    // Stage loader: 1024 x 16B chunks (A first 512, B next 512), 8 per thread.
    auto load_stage = [&](int kt) {
        char* stg = smem + (kt & (NST - 1)) * ST;
        const char* asrc = Abase + (size_t)kt * A_ST;
        const char* bsrc = Bbase + (size_t)kt * B_ST;
        #pragma unroll
        for (int i = 0; i < 4; i++) {
            int j = tid + i * NTHREADS;
            cp16(stg + j * 16, asrc + j * 16);
        }
        #pragma unroll
        for (int i = 0; i < 4; i++) {
            int j = tid + i * NTHREADS;
            cp16(stg + A_ST + j * 16, bsrc + j * 16);
        }
        asm volatile("cp.async.commit_group;");
    };

    load_stage(0); load_stage(1); load_stage(2);

    #pragma unroll 1
    for (int kt = 0; kt < NK; kt++) {
        // stage kt complete for this thread:
        if (kt < NK - 2)        asm volatile("cp.async.wait_group 2;");
        else if (kt == NK - 2)  asm volatile("cp.async.wait_group 1;");
        else                    asm volatile("cp.async.wait_group 0;");
        __syncthreads();   // stage kt globally visible; stage (kt-1) reads done

        if (kt + 3 < NK) load_stage(kt + 3);   // into the slot freed last iter

        const char* stg = smem + (kt & (NST - 1)) * ST;
        const char* sA = stg + (size_t)(warpM * 4) * 1024 + lane * 16;
        const char* sB = stg + A_ST + (size_t)(warpN * 8) * 512 + lane * 16;

        uint4 bf[8];
        #pragma unroll
        for (int nt = 0; nt < 8; nt++)
            bf[nt] = *(const uint4*)(sB + nt * 512);

        #pragma unroll
        for (int slab = 0; slab < 2; slab++) {
            uint4 af[4];
            #pragma unroll
            for (int mt = 0; mt < 4; mt++)
                af[mt] = *(const uint4*)(sA + mt * 1024 + slab * 512);
            #pragma unroll
            for (int mt = 0; mt < 4; mt++)
                #pragma unroll
                for (int nt = 0; nt < 8; nt++) {
                    unsigned b0 = slab ? bf[nt].z : bf[nt].x;
                    unsigned b1 = slab ? bf[nt].w : bf[nt].y;
                    mma_tf32(acc[mt][nt], af[mt].x, af[mt].y, af[mt].z, af[mt].w, b0, b1);
                }
        }
    }

    // ---- epilogue: C store + per-thread lse over own cols ----
    float lm[4][2], ls[4][2];
    #pragma unroll
    for (int mt = 0; mt < 4; mt++)
        #pragma unroll
        for (int sub = 0; sub < 2; sub++) { lm[mt][sub] = -CUDART_INF_F; ls[mt][sub] = 0.f; }

    #pragma unroll
    for (int mt = 0; mt < 4; mt++) {
        const int r0 = bm * TM + warpM * 64 + mt * 16 + grp;
        #pragma unroll
        for (int nt = 0; nt < 8; nt++) {
            const int c0 = bn * TN + warpN * 64 + nt * 8 + tg * 2;
            if (c0 < VV) {
                size_t base  = (size_t)r0 * VV + c0;
                size_t base2 = base + (size_t)8 * VV;
                C[base]  = acc[mt][nt][0];
                C[base2] = acc[mt][nt][2];
                if (c0 + 1 < VV) {
                    C[base + 1]  = acc[mt][nt][1];
                    C[base2 + 1] = acc[mt][nt][3];
                }
            }
            #pragma unroll
            for (int sub = 0; sub < 2; sub++) {
                #pragma unroll
                for (int cp = 0; cp < 2; cp++) {
                    if (c0 + cp < VV) {
                        float x = acc[mt][nt][sub * 2 + cp];
                        float& m = lm[mt][sub];
                        float& s = ls[mt][sub];
                        if (x > m) { s = s * __expf(m - x) + 1.f; m = x; }
                        else       { s += __expf(x - m); }
                    }
                }
            }
        }
    }
    // quad combine (lanes sharing grp, tg=0..3)
    #pragma unroll
    for (int mt = 0; mt < 4; mt++)
        #pragma unroll
        for (int sub = 0; sub < 2; sub++) {
            #pragma unroll
            for (int off = 1; off <= 2; off <<= 1) {
                float mo = __shfl_xor_sync(0xffffffffu, lm[mt][sub], off);
                float so = __shfl_xor_sync(0xffffffffu, ls[mt][sub], off);
                lse_comb(lm[mt][sub], ls[mt][sub], mo, so);
            }
        }
    if (tg == 0) {
        #pragma unroll
        for (int mt = 0; mt < 4; mt++)
            #pragma unroll
            for (int sub = 0; sub < 2; sub++) {
                int rl = warpM * 64 + mt * 16 + sub * 8 + grp;
                sbm[warpN][rl] = lm[mt][sub];
                sbs[warpN][rl] = ls[mt][sub];
            }
    }
    __syncthreads();
    // one thread per local row: combine the two warpN halves, write partials
    {
        float m = sbm[0][tid], s = sbs[0][tid];
        lse_comb(m, s, sbm[1][tid], sbs[1][tid]);
        size_t idx = (size_t)(bm * TM + tid) * NT + bn;
        part_m[idx] = m;
        part_s[idx] = s;
    }
}

// ---------------- loss from partials ----------------
__global__ void __launch_bounds__(128)
loss_partial_kernel(const float* __restrict__ C, const int* __restrict__ labels)
{
    const int r = blockIdx.x;               // 0..4093 shifted rows
    const int b = r / (TT - 1);
    const int t = r - b * (TT - 1);
    const int row = b * TT + t;

    float m = -CUDART_INF_F, s = 0.f;
    for (int j = threadIdx.x; j < NT; j += 128)
        lse_comb(m, s, part_m[(size_t)row * NT + j], part_s[(size_t)row * NT + j]);

    #pragma unroll
    for (int o = 16; o; o >>= 1) {
        float mo = __shfl_down_sync(0xffffffffu, m, o);
        float so = __shfl_down_sync(0xffffffffu, s, o);
        lse_comb(m, s, mo, so);
    }
    __shared__ float sm_[4], ss_[4];
    const int lane = threadIdx.x & 31, w = threadIdx.x >> 5;
    if (lane == 0) { sm_[w] = m; ss_[w] = s; }
    __syncthreads();
    if (threadIdx.x == 0) {
        m = sm_[0]; s = ss_[0];
        lse_comb(m, s, sm_[1], ss_[1]);
        lse_comb(m, s, sm_[2], ss_[2]);
        lse_comb(m, s, sm_[3], ss_[3]);
        int lbl = labels[row + 1];
        if (lbl < 0) lbl = 0;
        if (lbl >= VV) lbl = VV - 1;
        g_nll[r] = m + __logf(s) - C[(size_t)row * VV + lbl];
    }
}

__global__ void __launch_bounds__(256)
loss_reduce_kernel(float* __restrict__ out_loss)
{
    __shared__ float sh[256];
    float v = 0.f;
    for (int i = threadIdx.x; i < BB * (TT - 1); i += 256) v += g_nll[i];
    sh[threadIdx.x] = v;
    __syncthreads();
    for (int st = 128; st; st >>= 1) {
        if (threadIdx.x < st) sh[threadIdx.x] += sh[threadIdx.x + st];
        __syncthreads();
    }
    if (threadIdx.x == 0) *out_loss = sh[0] / (float)(BB * (TT - 1));
}

// ---------------- launch ----------------
extern "C" void kernel_launch(void* const* d_in, const int* in_sizes, int n_in,
                              void* d_out, int out_size)
{
    const float* hidden = nullptr;
    const float* weight = nullptr;
    const int*   labels = nullptr;
    for (int i = 0; i < n_in; i++) {
        if      (in_sizes[i] == MTOT * HH) hidden = (const float*)d_in[i];
        else if (in_sizes[i] == VV * HH)   weight = (const float*)d_in[i];
        else if (in_sizes[i] == BB * TT)   labels = (const int*)d_in[i];
    }
    float* out = (float*)d_out;

    cudaFuncSetAttribute(gemm_tf32_kernel,
                         cudaFuncAttributeMaxDynamicSharedMemorySize, SMEM_TOTAL);

    pack_A_kernel<<<(MTOT * HH / 4) / 256, 256>>>(hidden);
    pack_W_kernel<<<(NT * 64 * 512) / 256, 256>>>(weight);

    dim3 grid(MTOT / TM, NT);          // (32, 393)
    gemm_tf32_kernel<<<grid, NTHREADS, SMEM_TOTAL>>>(out);

    loss_partial_kernel<<<BB * (TT - 1), 128>>>(out, labels);
    loss_reduce_kernel<<<1, 256>>>(out + (size_t)out_size - 1);
}